// round 4
// baseline (speedup 1.0000x reference)
#include <cuda_runtime.h>
#include <cuda_fp16.h>

#define N_MAX 50000
#define E_TOT_MAX 860000   // E + N self loops
#define H 4
#define C 32
#define HC 128
#define NEG_SLOPE 0.2f
#define LDW 132            // padded smem stride (floats)

// Scratch (allocation-free rule: __device__ globals)
__device__ __half g_hh[N_MAX * HC];     // projected features, fp16 [N, H*C]
__device__ float  g_asrc[N_MAX * H];    // per-node src attention term
__device__ float  g_adst[N_MAX * H];    // per-node dst attention term
__device__ int    g_deg[N_MAX];         // in-degree (incl self loop)
__device__ int    g_cursor[N_MAX];      // placement cursor (start -> end)
__device__ int    g_srcs[E_TOT_MAX];    // CSR: src node per dst-grouped slot

__device__ __forceinline__ float leaky(float e) {
    return e > 0.f ? e : NEG_SLOPE * e;
}

__device__ __forceinline__ unsigned f2tf32(float f) {
    unsigned r;
    asm("cvt.rna.tf32.f32 %0, %1;" : "=r"(r) : "f"(f));
    return r;
}

__device__ __forceinline__ void mma_tf32(float* c, unsigned a0, unsigned a1,
                                         unsigned a2, unsigned a3,
                                         unsigned b0, unsigned b1) {
    asm volatile(
        "mma.sync.aligned.m16n8k8.row.col.f32.tf32.tf32.f32 "
        "{%0,%1,%2,%3}, {%4,%5,%6,%7}, {%8,%9}, {%0,%1,%2,%3};"
        : "+f"(c[0]), "+f"(c[1]), "+f"(c[2]), "+f"(c[3])
        : "r"(a0), "r"(a1), "r"(a2), "r"(a3), "r"(b0), "r"(b1));
}

// ---------------------------------------------------------------------------
// K0: deg = 1 (self loop)
// ---------------------------------------------------------------------------
__global__ void k_init(int N) {
    int tid = blockIdx.x * blockDim.x + threadIdx.x;
    if (tid < N) g_deg[tid] = 1;
}

// ---------------------------------------------------------------------------
// K1: h = x @ W via tf32 mma.sync. CTA = 128 nodes x 128 out-ch, K=128.
// 8 warps, warp w owns rows 16w..16w+15. x,W tf32-rounded in padded smem.
// Epilogue: stage accumulators to smem, compute asrc/adst, store h as fp16.
// ---------------------------------------------------------------------------
__global__ void __launch_bounds__(256, 1)
k_gemm(const float* __restrict__ x, const float* __restrict__ W,
       const float* __restrict__ att_src, const float* __restrict__ att_dst,
       int N) {
    extern __shared__ float sm[];
    float* xs = sm;                 // [128][LDW]  (reused as stage)
    float* Ws = sm + 128 * LDW;     // [128][LDW]

    int tid = threadIdx.x;
    int lane = tid & 31;
    int w = tid >> 5;
    int base = blockIdx.x * 128;

    // Load W [128][128] -> Ws (tf32-rounded), 256 threads x 16 float4
#pragma unroll
    for (int i = 0; i < 16; i++) {
        int idx = tid + i * 256;          // float4 index over 128x32
        int row = idx >> 5, col = idx & 31;
        float4 v = ((const float4*)W)[idx];
        float* dst = Ws + row * LDW + col * 4;
        dst[0] = __uint_as_float(f2tf32(v.x));
        dst[1] = __uint_as_float(f2tf32(v.y));
        dst[2] = __uint_as_float(f2tf32(v.z));
        dst[3] = __uint_as_float(f2tf32(v.w));
    }
    // Load x tile [128][128] -> xs (tf32-rounded, guarded)
#pragma unroll
    for (int i = 0; i < 16; i++) {
        int idx = tid + i * 256;
        int row = idx >> 5, col = idx & 31;
        int n = base + row;
        float4 v = make_float4(0.f, 0.f, 0.f, 0.f);
        if (n < N) v = ((const float4*)(x + (size_t)n * HC))[col];
        float* dst = xs + row * LDW + col * 4;
        dst[0] = __uint_as_float(f2tf32(v.x));
        dst[1] = __uint_as_float(f2tf32(v.y));
        dst[2] = __uint_as_float(f2tf32(v.z));
        dst[3] = __uint_as_float(f2tf32(v.w));
    }
    __syncthreads();

    // Accumulators: 16 n-tiles x 4 regs
    float c[64];
#pragma unroll
    for (int i = 0; i < 64; i++) c[i] = 0.f;

    int q = lane >> 2;       // 0..7
    int r = lane & 3;        // 0..3
    const float* arow0 = xs + (w * 16 + q) * LDW;
    const float* arow1 = xs + (w * 16 + q + 8) * LDW;

    for (int ks = 0; ks < 16; ks++) {
        int k0 = ks * 8;
        unsigned a0 = __float_as_uint(arow0[k0 + r]);
        unsigned a1 = __float_as_uint(arow1[k0 + r]);
        unsigned a2 = __float_as_uint(arow0[k0 + r + 4]);
        unsigned a3 = __float_as_uint(arow1[k0 + r + 4]);
        const float* b0p = Ws + (k0 + r) * LDW + q;
        const float* b1p = Ws + (k0 + r + 4) * LDW + q;
#pragma unroll
        for (int nt = 0; nt < 16; nt++) {
            unsigned b0 = __float_as_uint(b0p[nt * 8]);
            unsigned b1 = __float_as_uint(b1p[nt * 8]);
            mma_tf32(c + nt * 4, a0, a1, a2, a3, b0, b1);
        }
    }
    __syncthreads();

    // Stage results: c[nt][0..3] -> stage[row][col] (reuse xs, stride LDW)
    float* stage = xs;
#pragma unroll
    for (int nt = 0; nt < 16; nt++) {
        int col = nt * 8 + 2 * r;
        int row0 = w * 16 + q;
        stage[row0 * LDW + col]           = c[nt * 4 + 0];
        stage[row0 * LDW + col + 1]       = c[nt * 4 + 1];
        stage[(row0 + 8) * LDW + col]     = c[nt * 4 + 2];
        stage[(row0 + 8) * LDW + col + 1] = c[nt * 4 + 3];
    }
    __syncthreads();

    // Epilogue: tx owns 4 channels, ty covers 16 rows; store fp16 h + att terms
    int tx = lane;
    int ty = w;
    int head = tx >> 3;
    int part = tx & 7;
    float4 asv = ((const float4*)att_src)[head * 8 + part];
    float4 adv = ((const float4*)att_dst)[head * 8 + part];
#pragma unroll
    for (int j = 0; j < 16; j++) {
        int row = ty * 16 + j;
        int n = base + row;
        float4 hv = *(const float4*)(stage + row * LDW + tx * 4);
        if (n < N) {
            __half2 p0 = __floats2half2_rn(hv.x, hv.y);
            __half2 p1 = __floats2half2_rn(hv.z, hv.w);
            uint2 packed = make_uint2(*(unsigned*)&p0, *(unsigned*)&p1);
            ((uint2*)(g_hh + (size_t)n * HC))[tx] = packed;
        }
        float s = hv.x * asv.x + hv.y * asv.y + hv.z * asv.z + hv.w * asv.w;
        float d = hv.x * adv.x + hv.y * adv.y + hv.z * adv.z + hv.w * adv.w;
#pragma unroll
        for (int o = 4; o > 0; o >>= 1) {
            s += __shfl_xor_sync(0xffffffffu, s, o);
            d += __shfl_xor_sync(0xffffffffu, d, o);
        }
        if (part == 0 && n < N) {
            g_asrc[n * H + head] = s;
            g_adst[n * H + head] = d;
        }
    }
}

// ---------------------------------------------------------------------------
// CSR build: histogram -> single-block scan -> fill
// ---------------------------------------------------------------------------
__global__ void k_count(const int* __restrict__ ei, int E) {
    int eid = blockIdx.x * blockDim.x + threadIdx.x;
    if (eid < E) atomicAdd(&g_deg[ei[E + eid]], 1);
}

__global__ void k_scan(int N) {
    __shared__ int wsum[32];
    int t = threadIdx.x;
    int chunk = (N + 1023) >> 10;
    int lo = t * chunk;
    int hi = min(lo + chunk, N);
    int sum = 0;
    for (int i = lo; i < hi; i++) sum += g_deg[i];

    int lane = t & 31, wid = t >> 5;
    int v = sum;
#pragma unroll
    for (int o = 1; o < 32; o <<= 1) {
        int u = __shfl_up_sync(0xffffffffu, v, o);
        if (lane >= o) v += u;
    }
    if (lane == 31) wsum[wid] = v;
    __syncthreads();
    if (wid == 0) {
        int ws = wsum[lane];
#pragma unroll
        for (int o = 1; o < 32; o <<= 1) {
            int u = __shfl_up_sync(0xffffffffu, ws, o);
            if (lane >= o) ws += u;
        }
        wsum[lane] = ws;
    }
    __syncthreads();
    int run = v - sum + (wid > 0 ? wsum[wid - 1] : 0);  // exclusive prefix
    for (int i = lo; i < hi; i++) {
        g_cursor[i] = run;
        run += g_deg[i];
    }
}

__global__ void k_fill(const int* __restrict__ ei, int E, int N) {
    int eid = blockIdx.x * blockDim.x + threadIdx.x;
    if (eid >= E + N) return;
    int s, d;
    if (eid < E) { s = ei[eid]; d = ei[E + eid]; } else { s = d = eid - E; }
    int slot = atomicAdd(&g_cursor[d], 1);
    g_srcs[slot] = s;
}

// ---------------------------------------------------------------------------
// K4: single-pass online aggregation. One warp per dst node, zero atomics.
// Per edge: w = exp(leaky(asrc[s,hd] + adst[d,hd])); acc += w*h16[s]; dsum += w.
// dsum identical across the 8 lanes of a head (deterministic). out = acc/dsum.
// ---------------------------------------------------------------------------
__global__ void k_agg(float* __restrict__ out, const float* __restrict__ bias, int N) {
    int warp = (blockIdx.x * blockDim.x + threadIdx.x) >> 5;
    int lane = threadIdx.x & 31;
    if (warp >= N) return;
    int d = warp;

    int end = g_cursor[d];           // after fill: start + deg
    int deg = g_deg[d];
    int start = end - deg;

    int hd = lane >> 3;              // head of this lane's 4 channels
    float adst_h = g_adst[d * H + hd];

    float4 acc = make_float4(0.f, 0.f, 0.f, 0.f);
    float dsum = 0.f;

    int j = start;
    for (; j + 1 < end; j += 2) {
        int s0 = g_srcs[j];
        int s1 = g_srcs[j + 1];
        float w0 = __expf(leaky(g_asrc[s0 * H + hd] + adst_h));
        float w1 = __expf(leaky(g_asrc[s1 * H + hd] + adst_h));
        uint2 u0 = ((const uint2*)(g_hh + (size_t)s0 * HC))[lane];
        uint2 u1 = ((const uint2*)(g_hh + (size_t)s1 * HC))[lane];
        float2 f0a = __half22float2(*(__half2*)&u0.x);
        float2 f0b = __half22float2(*(__half2*)&u0.y);
        float2 f1a = __half22float2(*(__half2*)&u1.x);
        float2 f1b = __half22float2(*(__half2*)&u1.y);
        dsum += w0 + w1;
        acc.x += w0 * f0a.x + w1 * f1a.x;
        acc.y += w0 * f0a.y + w1 * f1a.y;
        acc.z += w0 * f0b.x + w1 * f1b.x;
        acc.w += w0 * f0b.y + w1 * f1b.y;
    }
    if (j < end) {
        int s0 = g_srcs[j];
        float w0 = __expf(leaky(g_asrc[s0 * H + hd] + adst_h));
        uint2 u0 = ((const uint2*)(g_hh + (size_t)s0 * HC))[lane];
        float2 f0a = __half22float2(*(__half2*)&u0.x);
        float2 f0b = __half22float2(*(__half2*)&u0.y);
        dsum += w0;
        acc.x += w0 * f0a.x;
        acc.y += w0 * f0a.y;
        acc.z += w0 * f0b.x;
        acc.w += w0 * f0b.y;
    }

    float rd = 1.0f / dsum;
    float4 bv = ((const float4*)bias)[lane];
    acc.x = acc.x * rd + bv.x;
    acc.y = acc.y * rd + bv.y;
    acc.z = acc.z * rd + bv.z;
    acc.w = acc.w * rd + bv.w;
    ((float4*)(out + (size_t)d * HC))[lane] = acc;
}

extern "C" void kernel_launch(void* const* d_in, const int* in_sizes, int n_in,
                              void* d_out, int out_size) {
    const float* x       = (const float*)d_in[0];
    const int*   ei      = (const int*)d_in[1];
    const float* W       = (const float*)d_in[2];
    const float* att_src = (const float*)d_in[3];
    const float* att_dst = (const float*)d_in[4];
    const float* bias    = (const float*)d_in[5];
    float* out = (float*)d_out;

    int N = in_sizes[0] / HC;
    int E = in_sizes[1] / 2;

    // GEMM + attention terms (tf32 MMA)
    {
        size_t smem = (size_t)(2 * 128 * LDW) * sizeof(float);  // 135168
        cudaFuncSetAttribute(k_gemm, cudaFuncAttributeMaxDynamicSharedMemorySize, (int)smem);
        k_gemm<<<(N + 127) / 128, 256, smem>>>(x, W, att_src, att_dst, N);
    }

    // CSR build
    k_init<<<(N + 255) / 256, 256>>>(N);
    k_count<<<(E + 255) / 256, 256>>>(ei, E);
    k_scan<<<1, 1024>>>(N);
    k_fill<<<(E + N + 255) / 256, 256>>>(ei, E, N);

    // Single-pass gather aggregation
    {
        long long threads = (long long)N * 32;
        int blocks = (int)((threads + 255) / 256);
        k_agg<<<blocks, 256>>>(out, bias, N);
    }
}

// round 5
// speedup vs baseline: 1.5238x; 1.5238x over previous
#include <cuda_runtime.h>
#include <cuda_fp16.h>

#define N_MAX 50000
#define E_TOT_MAX 860000   // E + N self loops
#define H 4
#define C 32
#define HC 128
#define NEG_SLOPE 0.2f
#define LDW 132            // padded smem stride (floats)

// Scratch (allocation-free rule: __device__ globals)
__device__ __half g_hh[N_MAX * HC];     // projected features, fp16 [N, H*C]
__device__ float  g_asrc[N_MAX * H];    // per-node src attention term
__device__ float  g_adst[N_MAX * H];    // per-node dst attention term
__device__ int    g_deg[N_MAX];         // in-degree (incl self loop)
__device__ int    g_cursor[N_MAX];      // placement cursor (start -> end)
__device__ int    g_srcs[E_TOT_MAX];    // CSR: src node per dst-grouped slot
__device__ int    g_total;              // running base for block-scan

__device__ __forceinline__ float leaky(float e) {
    return e > 0.f ? e : NEG_SLOPE * e;
}

__device__ __forceinline__ unsigned f2tf32(float f) {
    unsigned r;
    asm("cvt.rna.tf32.f32 %0, %1;" : "=r"(r) : "f"(f));
    return r;
}

__device__ __forceinline__ void mma_tf32(float* c, unsigned a0, unsigned a1,
                                         unsigned a2, unsigned a3,
                                         unsigned b0, unsigned b1) {
    asm volatile(
        "mma.sync.aligned.m16n8k8.row.col.f32.tf32.tf32.f32 "
        "{%0,%1,%2,%3}, {%4,%5,%6,%7}, {%8,%9}, {%0,%1,%2,%3};"
        : "+f"(c[0]), "+f"(c[1]), "+f"(c[2]), "+f"(c[3])
        : "r"(a0), "r"(a1), "r"(a2), "r"(a3), "r"(b0), "r"(b1));
}

// ---------------------------------------------------------------------------
// K0: deg = 1 (self loop), zero scan base
// ---------------------------------------------------------------------------
__global__ void k_init(int N) {
    int tid = blockIdx.x * blockDim.x + threadIdx.x;
    if (tid < N) g_deg[tid] = 1;
    if (tid == 0) g_total = 0;
}

// ---------------------------------------------------------------------------
// K1: h = x @ W via tf32 mma.sync. CTA = 128 nodes x 128 out-ch, K=128.
// Epilogue: stage to smem, compute asrc/adst, store h as fp16.
// ---------------------------------------------------------------------------
__global__ void __launch_bounds__(256, 1)
k_gemm(const float* __restrict__ x, const float* __restrict__ W,
       const float* __restrict__ att_src, const float* __restrict__ att_dst,
       int N) {
    extern __shared__ float sm[];
    float* xs = sm;                 // [128][LDW]  (reused as stage)
    float* Ws = sm + 128 * LDW;     // [128][LDW]

    int tid = threadIdx.x;
    int lane = tid & 31;
    int w = tid >> 5;
    int base = blockIdx.x * 128;

#pragma unroll
    for (int i = 0; i < 16; i++) {
        int idx = tid + i * 256;
        int row = idx >> 5, col = idx & 31;
        float4 v = ((const float4*)W)[idx];
        float* dst = Ws + row * LDW + col * 4;
        dst[0] = __uint_as_float(f2tf32(v.x));
        dst[1] = __uint_as_float(f2tf32(v.y));
        dst[2] = __uint_as_float(f2tf32(v.z));
        dst[3] = __uint_as_float(f2tf32(v.w));
    }
#pragma unroll
    for (int i = 0; i < 16; i++) {
        int idx = tid + i * 256;
        int row = idx >> 5, col = idx & 31;
        int n = base + row;
        float4 v = make_float4(0.f, 0.f, 0.f, 0.f);
        if (n < N) v = ((const float4*)(x + (size_t)n * HC))[col];
        float* dst = xs + row * LDW + col * 4;
        dst[0] = __uint_as_float(f2tf32(v.x));
        dst[1] = __uint_as_float(f2tf32(v.y));
        dst[2] = __uint_as_float(f2tf32(v.z));
        dst[3] = __uint_as_float(f2tf32(v.w));
    }
    __syncthreads();

    float c[64];
#pragma unroll
    for (int i = 0; i < 64; i++) c[i] = 0.f;

    int q = lane >> 2;
    int r = lane & 3;
    const float* arow0 = xs + (w * 16 + q) * LDW;
    const float* arow1 = xs + (w * 16 + q + 8) * LDW;

    for (int ks = 0; ks < 16; ks++) {
        int k0 = ks * 8;
        unsigned a0 = __float_as_uint(arow0[k0 + r]);
        unsigned a1 = __float_as_uint(arow1[k0 + r]);
        unsigned a2 = __float_as_uint(arow0[k0 + r + 4]);
        unsigned a3 = __float_as_uint(arow1[k0 + r + 4]);
        const float* b0p = Ws + (k0 + r) * LDW + q;
        const float* b1p = Ws + (k0 + r + 4) * LDW + q;
#pragma unroll
        for (int nt = 0; nt < 16; nt++) {
            unsigned b0 = __float_as_uint(b0p[nt * 8]);
            unsigned b1 = __float_as_uint(b1p[nt * 8]);
            mma_tf32(c + nt * 4, a0, a1, a2, a3, b0, b1);
        }
    }
    __syncthreads();

    float* stage = xs;
#pragma unroll
    for (int nt = 0; nt < 16; nt++) {
        int col = nt * 8 + 2 * r;
        int row0 = w * 16 + q;
        stage[row0 * LDW + col]           = c[nt * 4 + 0];
        stage[row0 * LDW + col + 1]       = c[nt * 4 + 1];
        stage[(row0 + 8) * LDW + col]     = c[nt * 4 + 2];
        stage[(row0 + 8) * LDW + col + 1] = c[nt * 4 + 3];
    }
    __syncthreads();

    int tx = lane;
    int ty = w;
    int head = tx >> 3;
    int part = tx & 7;
    float4 asv = ((const float4*)att_src)[head * 8 + part];
    float4 adv = ((const float4*)att_dst)[head * 8 + part];
#pragma unroll
    for (int j = 0; j < 16; j++) {
        int row = ty * 16 + j;
        int n = base + row;
        float4 hv = *(const float4*)(stage + row * LDW + tx * 4);
        if (n < N) {
            __half2 p0 = __floats2half2_rn(hv.x, hv.y);
            __half2 p1 = __floats2half2_rn(hv.z, hv.w);
            uint2 packed = make_uint2(*(unsigned*)&p0, *(unsigned*)&p1);
            ((uint2*)(g_hh + (size_t)n * HC))[tx] = packed;
        }
        float s = hv.x * asv.x + hv.y * asv.y + hv.z * asv.z + hv.w * asv.w;
        float d = hv.x * adv.x + hv.y * adv.y + hv.z * adv.z + hv.w * adv.w;
#pragma unroll
        for (int o = 4; o > 0; o >>= 1) {
            s += __shfl_xor_sync(0xffffffffu, s, o);
            d += __shfl_xor_sync(0xffffffffu, d, o);
        }
        if (part == 0 && n < N) {
            g_asrc[n * H + head] = s;
            g_adst[n * H + head] = d;
        }
    }
}

// ---------------------------------------------------------------------------
// CSR build: histogram -> parallel block-scan with atomic base -> fill
// Segment placement is atomic-order-dependent, but per-dst grouping (and
// thus the output) is unchanged.
// ---------------------------------------------------------------------------
__global__ void k_count(const int* __restrict__ ei, int E) {
    int eid = blockIdx.x * blockDim.x + threadIdx.x;
    if (eid < E) atomicAdd(&g_deg[ei[E + eid]], 1);
}

__global__ void k_scan(int N) {
    __shared__ int wsum[8];
    __shared__ int base_sm;
    int i = blockIdx.x * 256 + threadIdx.x;
    int lane = threadIdx.x & 31, wid = threadIdx.x >> 5;

    int v = (i < N) ? g_deg[i] : 0;
    int incl = v;
#pragma unroll
    for (int o = 1; o < 32; o <<= 1) {
        int u = __shfl_up_sync(0xffffffffu, incl, o);
        if (lane >= o) incl += u;
    }
    if (lane == 31) wsum[wid] = incl;
    __syncthreads();
    if (threadIdx.x == 0) {
        int run = 0;
#pragma unroll
        for (int k = 0; k < 8; k++) { int t = wsum[k]; wsum[k] = run; run += t; }
        base_sm = atomicAdd(&g_total, run);
    }
    __syncthreads();
    if (i < N) g_cursor[i] = base_sm + wsum[wid] + incl - v;  // exclusive start
}

__global__ void k_fill(const int* __restrict__ ei, int E, int N) {
    int eid = blockIdx.x * blockDim.x + threadIdx.x;
    if (eid >= E + N) return;
    int s, d;
    if (eid < E) { s = ei[eid]; d = ei[E + eid]; } else { s = d = eid - E; }
    int slot = atomicAdd(&g_cursor[d], 1);
    g_srcs[slot] = s;
}

// ---------------------------------------------------------------------------
// K4: single-pass online aggregation, one warp per dst, unroll-4 for MLP.
// ---------------------------------------------------------------------------
__global__ void k_agg(float* __restrict__ out, const float* __restrict__ bias, int N) {
    int warp = (blockIdx.x * blockDim.x + threadIdx.x) >> 5;
    int lane = threadIdx.x & 31;
    if (warp >= N) return;
    int d = warp;

    int end = g_cursor[d];           // after fill: start + deg
    int deg = g_deg[d];
    int start = end - deg;

    int hd = lane >> 3;
    float adst_h = g_adst[d * H + hd];

    float4 acc = make_float4(0.f, 0.f, 0.f, 0.f);
    float dsum = 0.f;

    int j = start;
    for (; j + 3 < end; j += 4) {
        int s0 = g_srcs[j], s1 = g_srcs[j + 1], s2 = g_srcs[j + 2], s3 = g_srcs[j + 3];
        float l0 = g_asrc[s0 * H + hd], l1 = g_asrc[s1 * H + hd];
        float l2 = g_asrc[s2 * H + hd], l3 = g_asrc[s3 * H + hd];
        uint2 u0 = ((const uint2*)(g_hh + (size_t)s0 * HC))[lane];
        uint2 u1 = ((const uint2*)(g_hh + (size_t)s1 * HC))[lane];
        uint2 u2 = ((const uint2*)(g_hh + (size_t)s2 * HC))[lane];
        uint2 u3 = ((const uint2*)(g_hh + (size_t)s3 * HC))[lane];
        float w0 = __expf(leaky(l0 + adst_h));
        float w1 = __expf(leaky(l1 + adst_h));
        float w2 = __expf(leaky(l2 + adst_h));
        float w3 = __expf(leaky(l3 + adst_h));
        dsum += (w0 + w1) + (w2 + w3);
        float2 a0 = __half22float2(*(__half2*)&u0.x), b0 = __half22float2(*(__half2*)&u0.y);
        float2 a1 = __half22float2(*(__half2*)&u1.x), b1 = __half22float2(*(__half2*)&u1.y);
        float2 a2 = __half22float2(*(__half2*)&u2.x), b2 = __half22float2(*(__half2*)&u2.y);
        float2 a3 = __half22float2(*(__half2*)&u3.x), b3 = __half22float2(*(__half2*)&u3.y);
        acc.x += w0 * a0.x + w1 * a1.x + w2 * a2.x + w3 * a3.x;
        acc.y += w0 * a0.y + w1 * a1.y + w2 * a2.y + w3 * a3.y;
        acc.z += w0 * b0.x + w1 * b1.x + w2 * b2.x + w3 * b3.x;
        acc.w += w0 * b0.y + w1 * b1.y + w2 * b2.y + w3 * b3.y;
    }
    for (; j < end; j++) {
        int s0 = g_srcs[j];
        float w0 = __expf(leaky(g_asrc[s0 * H + hd] + adst_h));
        uint2 u0 = ((const uint2*)(g_hh + (size_t)s0 * HC))[lane];
        float2 a0 = __half22float2(*(__half2*)&u0.x), b0 = __half22float2(*(__half2*)&u0.y);
        dsum += w0;
        acc.x += w0 * a0.x;
        acc.y += w0 * a0.y;
        acc.z += w0 * b0.x;
        acc.w += w0 * b0.y;
    }

    float rd = 1.0f / dsum;
    float4 bv = ((const float4*)bias)[lane];
    acc.x = acc.x * rd + bv.x;
    acc.y = acc.y * rd + bv.y;
    acc.z = acc.z * rd + bv.z;
    acc.w = acc.w * rd + bv.w;
    ((float4*)(out + (size_t)d * HC))[lane] = acc;
}

extern "C" void kernel_launch(void* const* d_in, const int* in_sizes, int n_in,
                              void* d_out, int out_size) {
    const float* x       = (const float*)d_in[0];
    const int*   ei      = (const int*)d_in[1];
    const float* W       = (const float*)d_in[2];
    const float* att_src = (const float*)d_in[3];
    const float* att_dst = (const float*)d_in[4];
    const float* bias    = (const float*)d_in[5];
    float* out = (float*)d_out;

    int N = in_sizes[0] / HC;
    int E = in_sizes[1] / 2;

    // GEMM + attention terms (tf32 MMA)
    {
        size_t smem = (size_t)(2 * 128 * LDW) * sizeof(float);  // 135168
        cudaFuncSetAttribute(k_gemm, cudaFuncAttributeMaxDynamicSharedMemorySize, (int)smem);
        k_gemm<<<(N + 127) / 128, 256, smem>>>(x, W, att_src, att_dst, N);
    }

    // CSR build
    k_init<<<(N + 255) / 256, 256>>>(N);
    k_count<<<(E + 255) / 256, 256>>>(ei, E);
    k_scan<<<(N + 255) / 256, 256>>>(N);
    k_fill<<<(E + N + 255) / 256, 256>>>(ei, E, N);

    // Single-pass gather aggregation
    {
        long long threads = (long long)N * 32;
        int blocks = (int)((threads + 255) / 256);
        k_agg<<<blocks, 256>>>(out, bias, N);
    }
}